// round 1
// baseline (speedup 1.0000x reference)
#include <cuda_runtime.h>
#include <cstdint>

#define N_NODES  50000
#define N_EDGES  800000
#define IN_DIM   1024
#define HID      512
#define N_CLASSES 6
#define N_GRAPHS 8
#define NEG_SLOPE 0.2f
#define EPS_DEN  1e-16f

// ---------------- scratch (allocation-free: device globals) ----------------
__device__ float    g_h  [(size_t)N_NODES * HID];   // post-GEMM features
__device__ float    g_out[(size_t)N_NODES * HID];   // aggregated output / next input
__device__ float    g_as [N_NODES];
__device__ float    g_ad [N_NODES];
__device__ float    g_e  [N_EDGES];                 // e, then ex
__device__ unsigned g_maxenc[N_NODES];
__device__ float    g_denom [N_NODES];
__device__ unsigned g_poolenc[N_GRAPHS * HID];

// order-preserving float<->uint encoding (for atomicMax on signed floats)
__device__ __forceinline__ unsigned enc_f(float f) {
    unsigned u = __float_as_uint(f);
    return (u & 0x80000000u) ? ~u : (u | 0x80000000u);
}
__device__ __forceinline__ float dec_f(unsigned e) {
    return __uint_as_float((e & 0x80000000u) ? (e & 0x7FFFFFFFu) : ~e);
}

// ---------------- SGEMM: C[M,512] = A[M,K] @ B[K,512], fp32 ----------------
// 64x64 tile, BK=16, 256 threads, 4x4 per thread.
__global__ __launch_bounds__(256) void sgemm64(
    const float* __restrict__ A, const float* __restrict__ B,
    float* __restrict__ C, int M, int K)
{
    const int N = HID;
    __shared__ float As[16][68];   // transposed: As[k][m]
    __shared__ float Bs[16][68];

    int tid = threadIdx.x;
    int bm = blockIdx.y * 64, bn = blockIdx.x * 64;
    int tm = (tid / 16) * 4, tn = (tid % 16) * 4;

    int la_row = tid >> 2;          // 0..63
    int la_col = (tid & 3) * 4;     // 0,4,8,12
    int lb_row = tid >> 4;          // 0..15
    int lb_col = (tid & 15) * 4;    // 0..60

    float acc[4][4] = {};

    for (int k0 = 0; k0 < K; k0 += 16) {
        float4 a4 = make_float4(0.f, 0.f, 0.f, 0.f);
        int arow = bm + la_row;
        if (arow < M)
            a4 = *reinterpret_cast<const float4*>(&A[(size_t)arow * K + k0 + la_col]);
        As[la_col + 0][la_row] = a4.x;
        As[la_col + 1][la_row] = a4.y;
        As[la_col + 2][la_row] = a4.z;
        As[la_col + 3][la_row] = a4.w;

        float4 b4 = *reinterpret_cast<const float4*>(&B[(size_t)(k0 + lb_row) * N + bn + lb_col]);
        *reinterpret_cast<float4*>(&Bs[lb_row][lb_col]) = b4;

        __syncthreads();
        #pragma unroll
        for (int k = 0; k < 16; k++) {
            float av[4], bv[4];
            #pragma unroll
            for (int i = 0; i < 4; i++) av[i] = As[k][tm + i];
            #pragma unroll
            for (int j = 0; j < 4; j++) bv[j] = Bs[k][tn + j];
            #pragma unroll
            for (int i = 0; i < 4; i++)
                #pragma unroll
                for (int j = 0; j < 4; j++)
                    acc[i][j] += av[i] * bv[j];
        }
        __syncthreads();
    }

    #pragma unroll
    for (int i = 0; i < 4; i++) {
        int row = bm + tm + i;
        if (row < M) {
            float4 c4 = make_float4(acc[i][0], acc[i][1], acc[i][2], acc[i][3]);
            *reinterpret_cast<float4*>(&C[(size_t)row * N + bn + tn]) = c4;
        }
    }
}

// -------- per-node attention scores + per-node softmax-state init ----------
__global__ void node_attn(const float* __restrict__ att_s, const float* __restrict__ att_d)
{
    int warp = (blockIdx.x * blockDim.x + threadIdx.x) >> 5;
    int lane = threadIdx.x & 31;
    if (warp >= N_NODES) return;
    const float* h = g_h + (size_t)warp * HID;
    float s = 0.f, d = 0.f;
    #pragma unroll
    for (int c = lane * 4; c < HID; c += 128) {
        float4 hv  = *reinterpret_cast<const float4*>(h + c);
        float4 as4 = *reinterpret_cast<const float4*>(att_s + c);
        float4 ad4 = *reinterpret_cast<const float4*>(att_d + c);
        s += hv.x * as4.x + hv.y * as4.y + hv.z * as4.z + hv.w * as4.w;
        d += hv.x * ad4.x + hv.y * ad4.y + hv.z * ad4.z + hv.w * ad4.w;
    }
    #pragma unroll
    for (int o = 16; o; o >>= 1) {
        s += __shfl_down_sync(0xFFFFFFFFu, s, o);
        d += __shfl_down_sync(0xFFFFFFFFu, d, o);
    }
    if (lane == 0) {
        g_as[warp] = s;
        g_ad[warp] = d;
        g_maxenc[warp] = 0u;     // below enc(-inf)=0x007FFFFF
        g_denom[warp] = 0.f;
    }
}

// ---------------- edge pass 1: e = leakyrelu, segment max -----------------
__global__ void edge_pass1(const int* __restrict__ src, const int* __restrict__ dst)
{
    int e = blockIdx.x * blockDim.x + threadIdx.x;
    if (e >= N_EDGES) return;
    int s = src[e], d = dst[e];
    float v = g_as[s] + g_ad[d];
    v = (v >= 0.f) ? v : NEG_SLOPE * v;
    g_e[e] = v;
    atomicMax(&g_maxenc[d], enc_f(v));
}

// ---------------- edge pass 2: ex = exp(e - m), segment sum ---------------
__global__ void edge_pass2(const int* __restrict__ dst)
{
    int e = blockIdx.x * blockDim.x + threadIdx.x;
    if (e >= N_EDGES) return;
    int d = dst[e];
    float m = dec_f(g_maxenc[d]);
    float ex = expf(g_e[e] - m);
    g_e[e] = ex;
    atomicAdd(&g_denom[d], ex);
}

// -------- edge pass 3: out[dst] += alpha * h[src]  (warp per edge) --------
__global__ __launch_bounds__(256) void edge_aggregate(
    const int* __restrict__ src, const int* __restrict__ dst)
{
    int warp = (blockIdx.x * 256 + threadIdx.x) >> 5;
    int lane = threadIdx.x & 31;
    if (warp >= N_EDGES) return;
    int s = src[warp], d = dst[warp];
    float alpha = g_e[warp] / (g_denom[d] + EPS_DEN);
    const float* hs = g_h + (size_t)s * HID;
    float* od = g_out + (size_t)d * HID;
    #pragma unroll
    for (int c0 = lane * 4; c0 < HID; c0 += 128) {
        float4 hv = *reinterpret_cast<const float4*>(hs + c0);
        float vx = alpha * hv.x, vy = alpha * hv.y, vz = alpha * hv.z, vw = alpha * hv.w;
        asm volatile("red.global.add.v4.f32 [%0], {%1, %2, %3, %4};"
                     :: "l"(od + c0), "f"(vx), "f"(vy), "f"(vz), "f"(vw)
                     : "memory");
    }
}

// ---------------- zero g_out ----------------------------------------------
__global__ void zero_out_kernel()
{
    size_t i = blockIdx.x * (size_t)blockDim.x + threadIdx.x;
    if (i < (size_t)N_NODES * HID / 4)
        reinterpret_cast<float4*>(g_out)[i] = make_float4(0.f, 0.f, 0.f, 0.f);
}

// ---------------- bias (+ optional relu), in place on g_out ---------------
__global__ void bias_act(const float* __restrict__ bias, int relu)
{
    size_t i = blockIdx.x * (size_t)blockDim.x + threadIdx.x;
    if (i >= (size_t)N_NODES * HID) return;
    int c = (int)(i & (HID - 1));
    float v = g_out[i] + bias[c];
    if (relu) v = fmaxf(v, 0.f);
    g_out[i] = v;
}

// ---------------- pooling -------------------------------------------------
__global__ void pool_init()
{
    int i = blockIdx.x * blockDim.x + threadIdx.x;
    if (i < N_GRAPHS * HID) g_poolenc[i] = 0u;
}

__global__ void pool_max(const int* __restrict__ batch)
{
    int c = blockIdx.x * blockDim.x + threadIdx.x;   // channel, grid.x*bdim = 512
    if (c >= HID) return;
    int n0 = blockIdx.y * 16;
    int curg = -1; float curmax = 0.f;
    for (int k = 0; k < 16; k++) {
        int n = n0 + k;
        if (n >= N_NODES) break;
        int g = __ldg(&batch[n]);
        float v = g_out[(size_t)n * HID + c];
        if (g != curg) {
            if (curg >= 0) atomicMax(&g_poolenc[curg * HID + c], enc_f(curmax));
            curg = g; curmax = v;
        } else {
            curmax = fmaxf(curmax, v);
        }
    }
    if (curg >= 0) atomicMax(&g_poolenc[curg * HID + c], enc_f(curmax));
}

// ---------------- final linear: out[8,6] = pooled @ Wlin + blin -----------
__global__ void final_linear(const float* __restrict__ Wlin,
                             const float* __restrict__ blin,
                             float* __restrict__ out)
{
    int g = blockIdx.x / N_CLASSES;
    int j = blockIdx.x % N_CLASSES;
    int lane = threadIdx.x;
    float s = 0.f;
    for (int c = lane; c < HID; c += 32) {
        float p = dec_f(g_poolenc[g * HID + c]);
        s += p * Wlin[c * N_CLASSES + j];
    }
    #pragma unroll
    for (int o = 16; o; o >>= 1) s += __shfl_down_sync(0xFFFFFFFFu, s, o);
    if (lane == 0) out[g * N_CLASSES + j] = s + blin[j];
}

// ---------------- host ----------------------------------------------------
extern "C" void kernel_launch(void* const* d_in, const int* in_sizes, int n_in,
                              void* d_out, int out_size)
{
    // identify inputs by element count (robust to metadata ordering)
    const float *x = nullptr, *W1 = nullptr, *W2 = nullptr, *W3 = nullptr;
    const float *Wlin = nullptr, *blin = nullptr;
    const int *edge_index = nullptr, *batch = nullptr;
    const float *v512[9] = {};
    int nv = 0;

    for (int i = 0; i < n_in; i++) {
        int sz = in_sizes[i];
        if      (sz == N_NODES * IN_DIM)      x = (const float*)d_in[i];
        else if (sz == 2 * N_EDGES)           edge_index = (const int*)d_in[i];
        else if (sz == N_NODES)               batch = (const int*)d_in[i];
        else if (sz == IN_DIM * HID)          W1 = (const float*)d_in[i];
        else if (sz == HID * HID)             { if (!W2) W2 = (const float*)d_in[i]; else W3 = (const float*)d_in[i]; }
        else if (sz == HID)                   { if (nv < 9) v512[nv++] = (const float*)d_in[i]; }
        else if (sz == HID * N_CLASSES)       Wlin = (const float*)d_in[i];
        else if (sz == N_CLASSES)             blin = (const float*)d_in[i];
    }
    const float *as1 = v512[0], *ad1 = v512[1], *b1 = v512[2];
    const float *as2 = v512[3], *ad2 = v512[4], *b2 = v512[5];
    const float *as3 = v512[6], *ad3 = v512[7], *b3 = v512[8];

    const int* src = edge_index;
    const int* dst = edge_index + N_EDGES;

    float *h_ptr = nullptr, *out_ptr = nullptr;
    cudaGetSymbolAddress((void**)&h_ptr, g_h);
    cudaGetSymbolAddress((void**)&out_ptr, g_out);

    const int ZERO_BLOCKS = (int)(((size_t)N_NODES * HID / 4 + 255) / 256);
    const int EW_BLOCKS   = (int)(((size_t)N_NODES * HID + 255) / 256);
    const int ATTN_BLOCKS = (N_NODES * 32 + 255) / 256;
    const int EDGE_BLOCKS = (N_EDGES + 255) / 256;
    const int AGG_BLOCKS  = (int)(((size_t)N_EDGES * 32 + 255) / 256);

    auto run_layer = [&](const float* X, int K, const float* W,
                         const float* as, const float* ad, const float* b, int relu) {
        dim3 gg(HID / 64, (N_NODES + 63) / 64);
        sgemm64<<<gg, 256>>>(X, W, h_ptr, N_NODES, K);
        zero_out_kernel<<<ZERO_BLOCKS, 256>>>();
        node_attn<<<ATTN_BLOCKS, 256>>>(as, ad);
        edge_pass1<<<EDGE_BLOCKS, 256>>>(src, dst);
        edge_pass2<<<EDGE_BLOCKS, 256>>>(dst);
        edge_aggregate<<<AGG_BLOCKS, 256>>>(src, dst);
        bias_act<<<EW_BLOCKS, 256>>>(b, relu);
    };

    run_layer(x,       IN_DIM, W1, as1, ad1, b1, 1);
    run_layer(out_ptr, HID,    W2, as2, ad2, b2, 1);
    run_layer(out_ptr, HID,    W3, as3, ad3, b3, 0);

    pool_init<<<(N_GRAPHS * HID + 255) / 256, 256>>>();
    dim3 pg(2, N_NODES / 16);
    pool_max<<<pg, 256>>>(batch);
    final_linear<<<N_GRAPHS * N_CLASSES, 32>>>(Wlin, blin, (float*)d_out);
}

// round 5
// speedup vs baseline: 1.5172x; 1.5172x over previous
#include <cuda_runtime.h>
#include <cuda_bf16.h>
#include <cstdint>

#define N_NODES  50000
#define N_EDGES  800000
#define IN_DIM   1024
#define HID      512
#define N_CLASSES 6
#define N_GRAPHS 8
#define NEG_SLOPE 0.2f
#define EPS_DEN  1e-16f

// ---------------- scratch (allocation-free: device globals) ----------------
__device__ float    g_h  [(size_t)N_NODES * HID];   // post-GEMM features
__device__ float    g_out[(size_t)N_NODES * HID];   // aggregated output / next input
__device__ float    g_as [N_NODES];
__device__ float    g_ad [N_NODES];
__device__ float    g_e  [N_EDGES];                 // e, then ex
__device__ unsigned g_maxenc[N_NODES];
__device__ float    g_denom [N_NODES];
__device__ unsigned g_poolenc[N_GRAPHS * HID];

// bf16 hi/lo operands for tensor-core GEMM (3-term fp32 emulation)
__device__ __align__(128) __nv_bfloat16 g_ahi[(size_t)N_NODES * IN_DIM];
__device__ __align__(128) __nv_bfloat16 g_alo[(size_t)N_NODES * IN_DIM];
__device__ __align__(128) __nv_bfloat16 g_bhi[(size_t)HID * IN_DIM];   // W^T [512, K]
__device__ __align__(128) __nv_bfloat16 g_blo[(size_t)HID * IN_DIM];

// order-preserving float<->uint encoding (for atomicMax on signed floats)
__device__ __forceinline__ unsigned enc_f(float f) {
    unsigned u = __float_as_uint(f);
    return (u & 0x80000000u) ? ~u : (u | 0x80000000u);
}
__device__ __forceinline__ float dec_f(unsigned e) {
    return __uint_as_float((e & 0x80000000u) ? (e & 0x7FFFFFFFu) : ~e);
}

// ======================= PTX helpers (baseline sm_100 ISA) =================
__device__ __forceinline__ uint32_t smem_u32(const void* p) {
    uint32_t a;
    asm("{ .reg .u64 t; cvta.to.shared.u64 t, %1; cvt.u32.u64 %0, t; }" : "=r"(a) : "l"(p));
    return a;
}
__device__ __forceinline__ void cp_async16(uint32_t dst, const void* src, int sz) {
    asm volatile("cp.async.cg.shared.global [%0], [%1], 16, %2;" :: "r"(dst), "l"(src), "r"(sz));
}
__device__ __forceinline__ void cp_commit() { asm volatile("cp.async.commit_group;" ::: "memory"); }
template <int N> __device__ __forceinline__ void cp_wait() {
    asm volatile("cp.async.wait_group %0;" :: "n"(N) : "memory");
}
__device__ __forceinline__ void ldsm4(uint32_t* r, uint32_t a) {
    asm volatile("ldmatrix.sync.aligned.m8n8.x4.shared.b16 {%0,%1,%2,%3}, [%4];"
                 : "=r"(r[0]), "=r"(r[1]), "=r"(r[2]), "=r"(r[3]) : "r"(a));
}
__device__ __forceinline__ void mma_bf16(float* c, const uint32_t* a, const uint32_t* b) {
    asm volatile("mma.sync.aligned.m16n8k16.row.col.f32.bf16.bf16.f32 "
                 "{%0,%1,%2,%3}, {%4,%5,%6,%7}, {%8,%9}, {%0,%1,%2,%3};"
                 : "+f"(c[0]), "+f"(c[1]), "+f"(c[2]), "+f"(c[3])
                 : "r"(a[0]), "r"(a[1]), "r"(a[2]), "r"(a[3]), "r"(b[0]), "r"(b[1]));
}

// ============ mma.sync bf16 GEMM: C[M,512] = A[M,K] @ W[K,512] =============
// A as (Ahi+Alo) [M,K] row-major bf16; B as W^T hi/lo [512,K] (i.e. col-major B).
// Per K-chunk: C += Ahi*Bhi + Ahi*Blo + Alo*Bhi  (fp32 accum).
#define BM 128
#define BN 128
#define BK 32
#define STAGES 3
#define ROW_B 80                           // 32 bf16 + 8 pad = 80 bytes per row
#define COMP_B (128 * ROW_B)               // 10240 bytes per component
#define STAGE_B (4 * COMP_B)               // Ahi,Alo,Bhi,Blo = 40960
#define GEMM_SMEM (STAGES * STAGE_B)       // 122880

__global__ __launch_bounds__(256, 1) void gemm_mma(
    const __nv_bfloat16* __restrict__ Ahi, const __nv_bfloat16* __restrict__ Alo,
    const __nv_bfloat16* __restrict__ Bhi, const __nv_bfloat16* __restrict__ Blo,
    float* __restrict__ C, int M, int K)
{
    extern __shared__ char sm[];
    const uint32_t sbase = smem_u32(sm);
    const int tid = threadIdx.x;
    const int lane = tid & 31, wid = tid >> 5;
    const int wm = wid & 3, wn = wid >> 2;          // warp tile: rows wm*32, cols wn*64
    const int bm = blockIdx.y, bn = blockIdx.x;
    const int NC = K / BK;

    const __nv_bfloat16* bases[4] = { Ahi, Alo, Bhi, Blo };

    auto load_chunk = [&](int c, int s) {
        int k0 = c * BK;
        uint32_t st = sbase + s * STAGE_B;
        #pragma unroll
        for (int comp = 0; comp < 4; comp++) {
            const __nv_bfloat16* base = bases[comp];
            #pragma unroll
            for (int j = 0; j < 2; j++) {
                int id  = tid + 256 * j;            // 0..511
                int row = id >> 2, c16 = id & 3;    // 128 rows x 4 x 16B
                int grow, valid;
                if (comp < 2) {
                    grow  = bm * BM + row;
                    valid = (grow < M) ? 16 : 0;
                    if (grow >= M) grow = M - 1;    // clamp: keep even dead addresses in-bounds
                } else {
                    grow  = bn * BN + row;
                    valid = 16;
                }
                const char* src = (const char*)(base + (size_t)grow * K + k0 + c16 * 8);
                cp_async16(st + comp * COMP_B + row * ROW_B + c16 * 16, src, valid);
            }
        }
        cp_commit();
    };

    float acc[2][8][4];
    #pragma unroll
    for (int i = 0; i < 2; i++)
        #pragma unroll
        for (int n = 0; n < 8; n++)
            #pragma unroll
            for (int q = 0; q < 4; q++) acc[i][n][q] = 0.f;

    load_chunk(0, 0);
    load_chunk(1, 1);

    for (int i = 0; i < NC; i++) {
        if (i + STAGES - 1 < NC) load_chunk(i + STAGES - 1, (i + STAGES - 1) % STAGES);
        else cp_commit();
        cp_wait<STAGES - 2>();
        __syncthreads();

        uint32_t sA = sbase + (i % STAGES) * STAGE_B;
        uint32_t sB = sA + 2 * COMP_B;

        #pragma unroll
        for (int ks = 0; ks < 2; ks++) {
            uint32_t fahi[2][4], falo[2][4], fbhi[8][2], fblo[8][2];
            // A fragments: x4 covers m16 x k16
            int arow  = wm * 32 + (lane & 15);
            int akoff = (ks * 16 + (lane >> 4) * 8) * 2;
            #pragma unroll
            for (int t2 = 0; t2 < 2; t2++) {
                uint32_t ad = sA + (arow + t2 * 16) * ROW_B + akoff;
                ldsm4(fahi[t2], ad);
                ldsm4(falo[t2], ad + COMP_B);
            }
            // B fragments: x4 covers 2 n-tiles x k16 (non-trans: rows = n of W^T)
            int mi = lane >> 3, r8 = lane & 7;
            #pragma unroll
            for (int j = 0; j < 4; j++) {
                int nrow  = wn * 64 + (2 * j + (mi >> 1)) * 8 + r8;
                int bkoff = (ks * 16 + (mi & 1) * 8) * 2;
                uint32_t bd = sB + nrow * ROW_B + bkoff;
                uint32_t r[4];
                ldsm4(r, bd);
                fbhi[2*j][0] = r[0]; fbhi[2*j][1] = r[1];
                fbhi[2*j+1][0] = r[2]; fbhi[2*j+1][1] = r[3];
                ldsm4(r, bd + COMP_B);
                fblo[2*j][0] = r[0]; fblo[2*j][1] = r[1];
                fblo[2*j+1][0] = r[2]; fblo[2*j+1][1] = r[3];
            }
            #pragma unroll
            for (int t2 = 0; t2 < 2; t2++)
                #pragma unroll
                for (int n = 0; n < 8; n++) {
                    mma_bf16(acc[t2][n], fahi[t2], fbhi[n]);
                    mma_bf16(acc[t2][n], fahi[t2], fblo[n]);
                    mma_bf16(acc[t2][n], falo[t2], fbhi[n]);
                }
        }
        __syncthreads();
    }

    // epilogue: c0,c1 -> (row, 2c); c2,c3 -> (row+8, 2c)
    #pragma unroll
    for (int t2 = 0; t2 < 2; t2++) {
        int row0 = bm * BM + wm * 32 + t2 * 16 + (lane >> 2);
        int col  = bn * BN + wn * 64 + (lane & 3) * 2;
        #pragma unroll
        for (int n = 0; n < 8; n++) {
            if (row0 < M)
                *reinterpret_cast<float2*>(&C[(size_t)row0 * HID + col + n * 8]) =
                    make_float2(acc[t2][n][0], acc[t2][n][1]);
            if (row0 + 8 < M)
                *reinterpret_cast<float2*>(&C[(size_t)(row0 + 8) * HID + col + n * 8]) =
                    make_float2(acc[t2][n][2], acc[t2][n][3]);
        }
    }
}

// ---------------- conversion kernels --------------------------------------
__global__ void conv_split(const float* __restrict__ src, __nv_bfloat16* __restrict__ hi,
                           __nv_bfloat16* __restrict__ lo, size_t n)
{
    size_t i = blockIdx.x * (size_t)blockDim.x + threadIdx.x;
    if (i >= n) return;
    float v = src[i];
    __nv_bfloat16 h = __float2bfloat16(v);
    hi[i] = h;
    lo[i] = __float2bfloat16(v - __bfloat162float(h));
}

// W [K, 512] fp32 -> W^T hi/lo [512, K] bf16
__global__ void conv_w(const float* __restrict__ W, __nv_bfloat16* __restrict__ hi,
                       __nv_bfloat16* __restrict__ lo, int K)
{
    int i = blockIdx.x * blockDim.x + threadIdx.x;
    if (i >= K * HID) return;
    int k = i >> 9, n = i & (HID - 1);
    float v = W[i];
    __nv_bfloat16 h = __float2bfloat16(v);
    hi[(size_t)n * K + k] = h;
    lo[(size_t)n * K + k] = __float2bfloat16(v - __bfloat162float(h));
}

// -------- per-node attention scores + per-node softmax-state init ----------
__global__ void node_attn(const float* __restrict__ att_s, const float* __restrict__ att_d)
{
    int warp = (blockIdx.x * blockDim.x + threadIdx.x) >> 5;
    int lane = threadIdx.x & 31;
    if (warp >= N_NODES) return;
    const float* h = g_h + (size_t)warp * HID;
    float s = 0.f, d = 0.f;
    #pragma unroll
    for (int c = lane * 4; c < HID; c += 128) {
        float4 hv  = *reinterpret_cast<const float4*>(h + c);
        float4 as4 = *reinterpret_cast<const float4*>(att_s + c);
        float4 ad4 = *reinterpret_cast<const float4*>(att_d + c);
        s += hv.x * as4.x + hv.y * as4.y + hv.z * as4.z + hv.w * as4.w;
        d += hv.x * ad4.x + hv.y * ad4.y + hv.z * ad4.z + hv.w * ad4.w;
    }
    #pragma unroll
    for (int o = 16; o; o >>= 1) {
        s += __shfl_down_sync(0xFFFFFFFFu, s, o);
        d += __shfl_down_sync(0xFFFFFFFFu, d, o);
    }
    if (lane == 0) {
        g_as[warp] = s;
        g_ad[warp] = d;
        g_maxenc[warp] = 0u;
        g_denom[warp] = 0.f;
    }
}

// ---------------- edge pass 1: e = leakyrelu, segment max -----------------
__global__ void edge_pass1(const int* __restrict__ src, const int* __restrict__ dst)
{
    int e = blockIdx.x * blockDim.x + threadIdx.x;
    if (e >= N_EDGES) return;
    int s = src[e], d = dst[e];
    float v = g_as[s] + g_ad[d];
    v = (v >= 0.f) ? v : NEG_SLOPE * v;
    g_e[e] = v;
    atomicMax(&g_maxenc[d], enc_f(v));
}

// ---------------- edge pass 2: ex = exp(e - m), segment sum ---------------
__global__ void edge_pass2(const int* __restrict__ dst)
{
    int e = blockIdx.x * blockDim.x + threadIdx.x;
    if (e >= N_EDGES) return;
    int d = dst[e];
    float m = dec_f(g_maxenc[d]);
    float ex = expf(g_e[e] - m);
    g_e[e] = ex;
    atomicAdd(&g_denom[d], ex);
}

// -------- edge pass 3: out[dst] += alpha * h[src]  (warp per edge) --------
__global__ __launch_bounds__(256) void edge_aggregate(
    const int* __restrict__ src, const int* __restrict__ dst)
{
    int warp = (blockIdx.x * 256 + threadIdx.x) >> 5;
    int lane = threadIdx.x & 31;
    if (warp >= N_EDGES) return;
    int s = src[warp], d = dst[warp];
    float alpha = g_e[warp] / (g_denom[d] + EPS_DEN);
    const float* hs = g_h + (size_t)s * HID;
    float* od = g_out + (size_t)d * HID;
    #pragma unroll
    for (int c0 = lane * 4; c0 < HID; c0 += 128) {
        float4 hv = *reinterpret_cast<const float4*>(hs + c0);
        float vx = alpha * hv.x, vy = alpha * hv.y, vz = alpha * hv.z, vw = alpha * hv.w;
        asm volatile("red.global.add.v4.f32 [%0], {%1, %2, %3, %4};"
                     :: "l"(od + c0), "f"(vx), "f"(vy), "f"(vz), "f"(vw)
                     : "memory");
    }
}

// ---------------- zero g_out ----------------------------------------------
__global__ void zero_out_kernel()
{
    size_t i = blockIdx.x * (size_t)blockDim.x + threadIdx.x;
    if (i < (size_t)N_NODES * HID / 4)
        reinterpret_cast<float4*>(g_out)[i] = make_float4(0.f, 0.f, 0.f, 0.f);
}

// -------- bias (+relu), in place on g_out, optionally emit bf16 hi/lo -----
__global__ void bias_act(const float* __restrict__ bias, int relu, int doconv)
{
    size_t i = blockIdx.x * (size_t)blockDim.x + threadIdx.x;
    if (i >= (size_t)N_NODES * HID) return;
    int c = (int)(i & (HID - 1));
    float v = g_out[i] + bias[c];
    if (relu) v = fmaxf(v, 0.f);
    g_out[i] = v;
    if (doconv) {
        __nv_bfloat16 h = __float2bfloat16(v);
        g_ahi[i] = h;
        g_alo[i] = __float2bfloat16(v - __bfloat162float(h));
    }
}

// ---------------- pooling -------------------------------------------------
__global__ void pool_init()
{
    int i = blockIdx.x * blockDim.x + threadIdx.x;
    if (i < N_GRAPHS * HID) g_poolenc[i] = 0u;
}

__global__ void pool_max(const int* __restrict__ batch)
{
    int c = blockIdx.x * blockDim.x + threadIdx.x;
    if (c >= HID) return;
    int n0 = blockIdx.y * 16;
    int curg = -1; float curmax = 0.f;
    for (int k = 0; k < 16; k++) {
        int n = n0 + k;
        if (n >= N_NODES) break;
        int g = __ldg(&batch[n]);
        float v = g_out[(size_t)n * HID + c];
        if (g != curg) {
            if (curg >= 0) atomicMax(&g_poolenc[curg * HID + c], enc_f(curmax));
            curg = g; curmax = v;
        } else {
            curmax = fmaxf(curmax, v);
        }
    }
    if (curg >= 0) atomicMax(&g_poolenc[curg * HID + c], enc_f(curmax));
}

// ---------------- final linear: out[8,6] = pooled @ Wlin + blin -----------
__global__ void final_linear(const float* __restrict__ Wlin,
                             const float* __restrict__ blin,
                             float* __restrict__ out)
{
    int g = blockIdx.x / N_CLASSES;
    int j = blockIdx.x % N_CLASSES;
    int lane = threadIdx.x;
    float s = 0.f;
    for (int c = lane; c < HID; c += 32) {
        float p = dec_f(g_poolenc[g * HID + c]);
        s += p * Wlin[c * N_CLASSES + j];
    }
    #pragma unroll
    for (int o = 16; o; o >>= 1) s += __shfl_down_sync(0xFFFFFFFFu, s, o);
    if (lane == 0) out[g * N_CLASSES + j] = s + blin[j];
}

// ---------------- host ----------------------------------------------------
extern "C" void kernel_launch(void* const* d_in, const int* in_sizes, int n_in,
                              void* d_out, int out_size)
{
    const float *x = nullptr, *W1 = nullptr, *W2 = nullptr, *W3 = nullptr;
    const float *Wlin = nullptr, *blin = nullptr;
    const int *edge_index = nullptr, *batch = nullptr;
    const float *v512[9] = {};
    int nv = 0;

    for (int i = 0; i < n_in; i++) {
        int sz = in_sizes[i];
        if      (sz == N_NODES * IN_DIM)      x = (const float*)d_in[i];
        else if (sz == 2 * N_EDGES)           edge_index = (const int*)d_in[i];
        else if (sz == N_NODES)               batch = (const int*)d_in[i];
        else if (sz == IN_DIM * HID)          W1 = (const float*)d_in[i];
        else if (sz == HID * HID)             { if (!W2) W2 = (const float*)d_in[i]; else W3 = (const float*)d_in[i]; }
        else if (sz == HID)                   { if (nv < 9) v512[nv++] = (const float*)d_in[i]; }
        else if (sz == HID * N_CLASSES)       Wlin = (const float*)d_in[i];
        else if (sz == N_CLASSES)             blin = (const float*)d_in[i];
    }
    const float *as1 = v512[0], *ad1 = v512[1], *b1 = v512[2];
    const float *as2 = v512[3], *ad2 = v512[4], *b2 = v512[5];
    const float *as3 = v512[6], *ad3 = v512[7], *b3 = v512[8];

    const int* src = edge_index;
    const int* dst = edge_index + N_EDGES;

    float *h_ptr = nullptr, *out_ptr = nullptr;
    __nv_bfloat16 *ahi = nullptr, *alo = nullptr, *bhi = nullptr, *blo = nullptr;
    cudaGetSymbolAddress((void**)&h_ptr, g_h);
    cudaGetSymbolAddress((void**)&out_ptr, g_out);
    cudaGetSymbolAddress((void**)&ahi, g_ahi);
    cudaGetSymbolAddress((void**)&alo, g_alo);
    cudaGetSymbolAddress((void**)&bhi, g_bhi);
    cudaGetSymbolAddress((void**)&blo, g_blo);

    // set every call (no static guards allowed); not a stream op, capture-safe
    cudaFuncSetAttribute(gemm_mma, cudaFuncAttributeMaxDynamicSharedMemorySize, GEMM_SMEM);

    const int ZERO_BLOCKS = (int)(((size_t)N_NODES * HID / 4 + 255) / 256);
    const int EW_BLOCKS   = (int)(((size_t)N_NODES * HID + 255) / 256);
    const int ATTN_BLOCKS = (N_NODES * 32 + 255) / 256;
    const int EDGE_BLOCKS = (N_EDGES + 255) / 256;
    const int AGG_BLOCKS  = (int)(((size_t)N_EDGES * 32 + 255) / 256);
    const int NTM = (N_NODES + BM - 1) / BM;

    auto run_layer = [&](int K, const float* W,
                         const float* as, const float* ad, const float* b,
                         int relu, int conv_next) {
        conv_w<<<(K * HID + 255) / 256, 256>>>(W, bhi, blo, K);
        gemm_mma<<<dim3(HID / BN, NTM), 256, GEMM_SMEM>>>(ahi, alo, bhi, blo, h_ptr, N_NODES, K);
        zero_out_kernel<<<ZERO_BLOCKS, 256>>>();
        node_attn<<<ATTN_BLOCKS, 256>>>(as, ad);
        edge_pass1<<<EDGE_BLOCKS, 256>>>(src, dst);
        edge_pass2<<<EDGE_BLOCKS, 256>>>(dst);
        edge_aggregate<<<AGG_BLOCKS, 256>>>(src, dst);
        bias_act<<<EW_BLOCKS, 256>>>(b, relu, conv_next);
    };

    // layer 1: split x into bf16 hi/lo
    size_t nx = (size_t)N_NODES * IN_DIM;
    conv_split<<<(int)((nx + 255) / 256), 256>>>(x, ahi, alo, nx);
    run_layer(IN_DIM, W1, as1, ad1, b1, 1, 1);   // bias_act emits hi/lo for layer 2
    run_layer(HID,    W2, as2, ad2, b2, 1, 1);   // emits hi/lo for layer 3
    run_layer(HID,    W3, as3, ad3, b3, 0, 0);

    pool_init<<<(N_GRAPHS * HID + 255) / 256, 256>>>();
    dim3 pg(2, N_NODES / 16);
    pool_max<<<pg, 256>>>(batch);
    final_linear<<<N_GRAPHS * N_CLASSES, 32>>>(Wlin, blin, (float*)d_out);
}